// round 3
// baseline (speedup 1.0000x reference)
#include <cuda_runtime.h>
#include <cuda_bf16.h>
#include <float.h>

#define B_    64
#define T_    256
#define V_    6625
#define S_    25
#define SXP_  52              // padded emit row stride (floats)
#define NEG_  (-1e30f)
#define NPROD 140             // producer blocks
#define NBLK  148             // total blocks (co-resident: 1 block/SM)
#define NWP   (NPROD * 8)     // producer warps

// Scratch (no allocations -> __device__ globals; zero-initialized at load)
__device__ float    g_emit[B_ * T_ * SXP_];
__device__ float    g_loss[B_];
__device__ unsigned g_flag[B_ * T_];   // flag[t*64+b]; self-resetting each run
__device__ unsigned g_cnt;             // completion counter; self-resetting

__device__ __forceinline__ unsigned ld_acq(const unsigned* p) {
    unsigned v;
    asm volatile("ld.acquire.gpu.global.u32 %0, [%1];" : "=r"(v) : "l"(p) : "memory");
    return v;
}
__device__ __forceinline__ void st_rel(unsigned* p, unsigned v) {
    asm volatile("st.release.gpu.global.u32 [%0], %1;" :: "l"(p), "r"(v) : "memory");
}

__device__ __forceinline__ float lse2f(float a, float b) {
    float m = fmaxf(a, b);
    return m + __logf(__expf(a - m) + __expf(b - m));
}
__device__ __forceinline__ float lse3f(float a, float b, float c) {
    float m = fmaxf(a, fmaxf(b, c));
    return m + __logf(__expf(a - m) + __expf(b - m) + __expf(c - m));
}

// ---------------------------------------------------------------------------
// Producer: one WARP per (b,t) row. Online (streaming) logsumexp over V with
// U=8 float4 pipeline; no block barriers -> 8 independent streams per SM.
// ---------------------------------------------------------------------------
__device__ void producer(const float* __restrict__ pred,
                         const int*   __restrict__ target) {
    const int wid  = (blockIdx.x << 3) + (threadIdx.x >> 5);
    const int lane = threadIdx.x & 31;

    for (int r = wid; r < B_ * T_; r += NWP) {
        const int t = r >> 6;          // production order: t-major
        const int b = r & 63;
        const size_t base = ((size_t)b * T_ + t) * V_;
        const float* __restrict__ row = pred + base;

        const int head  = (int)((4 - (base & 3)) & 3);
        const int nv4   = (V_ - head) >> 2;
        const int ntail = V_ - head - (nv4 << 2);
        const float4* __restrict__ rv = reinterpret_cast<const float4*>(row + head);

        float hv = (lane < head)  ? row[lane] : -FLT_MAX;
        float tv = (lane < ntail) ? row[head + (nv4 << 2) + lane] : -FLT_MAX;
        float m = fmaxf(hv, tv);
        float s = __expf(hv - m) + __expf(tv - m);

        int g = lane;
        const int nfull = nv4 >> 8;    // 256 float4 per iteration (8 per lane)
        for (int it = 0; it < nfull; ++it) {
            float4 v0 = rv[g +   0], v1 = rv[g +  32], v2 = rv[g +  64], v3 = rv[g +  96];
            float4 v4 = rv[g + 128], v5 = rv[g + 160], v6 = rv[g + 192], v7 = rv[g + 224];
            g += 256;
            float m0 = fmaxf(fmaxf(v0.x, v0.y), fmaxf(v0.z, v0.w));
            float m1 = fmaxf(fmaxf(v1.x, v1.y), fmaxf(v1.z, v1.w));
            float m2 = fmaxf(fmaxf(v2.x, v2.y), fmaxf(v2.z, v2.w));
            float m3 = fmaxf(fmaxf(v3.x, v3.y), fmaxf(v3.z, v3.w));
            float m4 = fmaxf(fmaxf(v4.x, v4.y), fmaxf(v4.z, v4.w));
            float m5 = fmaxf(fmaxf(v5.x, v5.y), fmaxf(v5.z, v5.w));
            float m6 = fmaxf(fmaxf(v6.x, v6.y), fmaxf(v6.z, v6.w));
            float m7 = fmaxf(fmaxf(v7.x, v7.y), fmaxf(v7.z, v7.w));
            float lm = fmaxf(fmaxf(fmaxf(m0, m1), fmaxf(m2, m3)),
                             fmaxf(fmaxf(m4, m5), fmaxf(m6, m7)));
            float nm = fmaxf(m, lm);
            float sc = __expf(m - nm);
            float p0 = __expf(v0.x - nm) + __expf(v0.y - nm) + __expf(v0.z - nm) + __expf(v0.w - nm);
            float p1 = __expf(v1.x - nm) + __expf(v1.y - nm) + __expf(v1.z - nm) + __expf(v1.w - nm);
            float p2 = __expf(v2.x - nm) + __expf(v2.y - nm) + __expf(v2.z - nm) + __expf(v2.w - nm);
            float p3 = __expf(v3.x - nm) + __expf(v3.y - nm) + __expf(v3.z - nm) + __expf(v3.w - nm);
            float p4 = __expf(v4.x - nm) + __expf(v4.y - nm) + __expf(v4.z - nm) + __expf(v4.w - nm);
            float p5 = __expf(v5.x - nm) + __expf(v5.y - nm) + __expf(v5.z - nm) + __expf(v5.w - nm);
            float p6 = __expf(v6.x - nm) + __expf(v6.y - nm) + __expf(v6.z - nm) + __expf(v6.w - nm);
            float p7 = __expf(v7.x - nm) + __expf(v7.y - nm) + __expf(v7.z - nm) + __expf(v7.w - nm);
            float ps = ((p0 + p1) + (p2 + p3)) + ((p4 + p5) + (p6 + p7));
            s = fmaf(s, sc, ps);
            m = nm;
        }
        for (; g < nv4; g += 32) {     // per-lane remainder float4s
            float4 v = rv[g];
            float lm = fmaxf(fmaxf(v.x, v.y), fmaxf(v.z, v.w));
            float nm = fmaxf(m, lm);
            float sc = __expf(m - nm);
            s = fmaf(s, sc, __expf(v.x - nm) + __expf(v.y - nm)
                          + __expf(v.z - nm) + __expf(v.w - nm));
            m = nm;
        }

        // Warp butterfly merge -> all lanes hold (m, s)
#pragma unroll
        for (int off = 16; off > 0; off >>= 1) {
            float mo = __shfl_xor_sync(0xffffffffu, m, off);
            float so = __shfl_xor_sync(0xffffffffu, s, off);
            float nm = fmaxf(m, mo);
            s = s * __expf(m - nm) + so * __expf(mo - nm);
            m = nm;
        }
        const float lse = m + __logf(s);

        // Gather 51 extended-label emissions + pad slot 51
        float* __restrict__ eout = g_emit + (size_t)(b * T_ + t) * SXP_;
        {
            int e = lane;                                   // 0..31 (< 51)
            int lab = (e & 1) ? target[b * S_ + (e >> 1)] : 0;
            eout[e] = row[lab] - lse;
            int e2 = lane + 32;                             // 32..63
            if (e2 < SXP_) {
                float val = NEG_;
                if (e2 < 51) {
                    int lab2 = (e2 & 1) ? target[b * S_ + (e2 >> 1)] : 0;
                    val = row[lab2] - lse;
                }
                eout[e2] = val;
            }
        }
        __threadfence();
        __syncwarp();
        if (lane == 0) st_rel(&g_flag[r], 1u);
    }
}

// ---------------------------------------------------------------------------
// Consumer: one WARP per batch. Lane i holds states (2i, 2i+1). Spins on the
// producer flags; prefetches e(t+1) + flag(t+2) to hide L2 latency behind the
// lse chain. Resets every flag it consumes (replay-safe).
// ---------------------------------------------------------------------------
__device__ void consumer(const int* __restrict__ target,
                         const int* __restrict__ length,
                         float* __restrict__ out) {
    const int b = ((blockIdx.x - NPROD) << 3) + (threadIdx.x >> 5);  // 0..63
    const int lane = threadIdx.x & 31;
    const bool act = (lane < 26);
    const float2 nf2 = make_float2(NEG_, NEG_);

    bool skip_hi = false;
    if (lane > 0 && lane < 25)
        skip_hi = (target[b * S_ + lane] != target[b * S_ + lane - 1]);

    const float2* __restrict__ ep =
        reinterpret_cast<const float2*>(g_emit) + (size_t)(b * T_) * (SXP_ / 2) + lane;
    unsigned* fl = g_flag + b;                 // flag index: t*64 (+b folded in)
    volatile unsigned* flv = fl;

    // t = 0
    while (ld_acq(fl + 0) == 0) {}
    flv[0] = 0;
    float2 e0 = act ? __ldcg(ep) : nf2;
    float lo = (lane == 0) ? e0.x : NEG_;
    float hi = (lane == 0) ? e0.y : NEG_;

    // t = 1 data
    while (ld_acq(fl + 64) == 0) {}
    flv[64] = 0;
    float2 ecur = act ? __ldcg(ep + (SXP_ / 2)) : nf2;
    unsigned fnxt = ld_acq(fl + 128);

#pragma unroll 1
    for (int t = 1; t < T_; ++t) {
        float2 enxt = nf2;
        if (t + 1 < T_) {
            const int i = (t + 1) << 6;
            if (fnxt == 0) { while (ld_acq(fl + i) == 0) {} }
            flv[i] = 0;
            if (act) enxt = __ldcg(ep + (size_t)(t + 1) * (SXP_ / 2));
            fnxt = (t + 2 < T_) ? ld_acq(fl + ((t + 2) << 6)) : 1u;
        }
        // recursion step (overlaps with enxt load)
        float p_hi = __shfl_up_sync(0xffffffffu, hi, 1);
        if (lane == 0) p_hi = NEG_;
        float nlo = lse2f(lo, p_hi) + ecur.x;
        float a3  = skip_hi ? p_hi : NEG_;
        float nhi = lse3f(hi, lo, a3) + ecur.y;
        lo = nlo; hi = nhi;
        ecur = enxt;
    }

    // Final: ll = logsumexp(alpha[2L-1], alpha[2L])
    const int L = length[b];
    float ah = __shfl_sync(0xffffffffu, hi, L - 1);   // state 2L-1 (lane L-1 hi)
    float al = __shfl_sync(0xffffffffu, lo, L);       // state 2L   (lane L   lo)

    int cdone = 0;
    if (lane == 0) {
        float m  = fmaxf(ah, al);
        float ll = m + logf(expf(ah - m) + expf(al - m));
        float loss = -ll;
        if (!isfinite(loss)) loss = 0.f;
        g_loss[b] = loss / (float)L;
        __threadfence();
        cdone = (int)atomicAdd(&g_cnt, 1u);
    }
    cdone = __shfl_sync(0xffffffffu, cdone, 0);

    if (cdone == B_ - 1) {            // last warp: deterministic final reduce
        __threadfence();
        float v = g_loss[lane] + g_loss[lane + 32];
#pragma unroll
        for (int off = 16; off > 0; off >>= 1)
            v += __shfl_down_sync(0xffffffffu, v, off);
        if (lane == 0) {
            out[0] = v / (float)B_;
            atomicExch(&g_cnt, 0u);   // reset for next replay
        }
    }
}

// ---------------------------------------------------------------------------
__global__ __launch_bounds__(256, 1)
void ctc_fused_kernel(const float* __restrict__ pred,
                      const int*   __restrict__ target,
                      const int*   __restrict__ length,
                      float* __restrict__ out) {
    if (blockIdx.x < NPROD) producer(pred, target);
    else                    consumer(target, length, out);
}

extern "C" void kernel_launch(void* const* d_in, const int* in_sizes, int n_in,
                              void* d_out, int out_size) {
    const float* pred   = (const float*)d_in[0];
    const int*   target = (const int*)d_in[1];
    const int*   length = (const int*)d_in[2];
    float* out = (float*)d_out;

    ctc_fused_kernel<<<NBLK, 256>>>(pred, target, length, out);
}